// round 15
// baseline (speedup 1.0000x reference)
#include <cuda_runtime.h>

#define N 2048
#define K 16
#define BATCH 16384
#define RPB 16
#define THREADS 512
#define GRID_MAIN 152
#define NTILES (BATCH / RPB)
#define STAGES 8
#define INFLIGHT 6   // wait_group 6 -> 7 groups (3.5 KB) in flight per warp

// Final composed weights, layout [t][m4][rho][4]:
//   g_Wfin[((t*4 + (m>>2))*128 + rho)*4 + (m&3)]
__device__ float g_Wfin[K * K * 128];

// ---------------------------------------------------------------------------
// PDL primitives
// ---------------------------------------------------------------------------
__device__ __forceinline__ void pdl_launch_dependents() {
    asm volatile("griddepcontrol.launch_dependents;" ::: "memory");
}
__device__ __forceinline__ void pdl_wait() {
    asm volatile("griddepcontrol.wait;" ::: "memory");
}

// ---------------------------------------------------------------------------
// Fast compose: Wfin = scaling * (W0 @ W1 @ W2), smem-staged tables.
// 16 blocks x 256 threads; block b owns rows [128b, 128b+128).
//   Phase 1: stage FULL v1 (32K floats) in smem; compute W01 slice from smem
//            (inner loop is LDS, not scattered LDG -> latency chain removed).
//   Phase 2: stage FULL v2 in the same smem; compute Wfin slice.
// Composed pattern: c = (r + 128*s + 3) % N; r = rho + 128*t, m = (t+s)&15.
// smem: 32768 (table) + 128*17 (W01, pad vs bank conflicts) floats = 137 KB.
// ---------------------------------------------------------------------------
#define CSM_TAB 0
#define CSM_W01 32768
#define CSM_FLOATS (32768 + 128 * 17)

__global__ void __maxnreg__(64) k_compose(
        const float* __restrict__ v0, const float* __restrict__ v1,
        const float* __restrict__ v2, const float* __restrict__ scaling) {
    pdl_launch_dependents();

    extern __shared__ float cs[];
    const int tid = threadIdx.x;
    const int s   = tid & 15;
    const int rl0 = tid >> 4;                   // 0..15
    const int r0  = blockIdx.x * 128;

    // Stage full v1 table (coalesced float4: 8192 ld / 256 thr = 32 each)
    {
        const float4* src = (const float4*)v1;
        float4* dst = (float4*)(cs + CSM_TAB);
#pragma unroll
        for (int i = tid; i < (N * K) / 4; i += 256) dst[i] = src[i];
    }
    __syncthreads();

    // Stage 1: W01[r, s] = sum_k0 v0[r,k0] * v1[(r+128k0)%N, (s-k0)&15]
#pragma unroll
    for (int j = 0; j < 8; j++) {
        const int rl = j * 16 + rl0;            // 0..127
        const int r  = r0 + rl;
        float acc = 0.f;
#pragma unroll
        for (int k0 = 0; k0 < K; k0++) {
            int arow = (r + 128 * k0) & (N - 1);
            acc = fmaf(v0[r * K + k0], cs[CSM_TAB + arow * K + ((s - k0) & (K - 1))], acc);
        }
        cs[CSM_W01 + rl * 17 + s] = acc;
    }
    __syncthreads();

    // Stage full v2 table over the v1 area
    {
        const float4* src = (const float4*)v2;
        float4* dst = (float4*)(cs + CSM_TAB);
#pragma unroll
        for (int i = tid; i < (N * K) / 4; i += 256) dst[i] = src[i];
    }
    __syncthreads();

    // Stage 2: Wfin, folded with scaling, written in [t][m4][rho][4] layout
    const float sc = scaling[0];
#pragma unroll
    for (int j = 0; j < 8; j++) {
        const int rl = j * 16 + rl0;
        const int r  = r0 + rl;
        float acc = 0.f;
#pragma unroll
        for (int s01 = 0; s01 < K; s01++) {
            int brow = (r + 128 * s01 + 1) & (N - 1);
            acc = fmaf(cs[CSM_W01 + rl * 17 + s01],
                       cs[CSM_TAB + brow * K + ((s - s01) & (K - 1))], acc);
        }
        int rho = r & 127;
        int t   = r >> 7;
        int m   = (t + s) & (K - 1);
        g_Wfin[((t * 4 + (m >> 2)) * 128 + rho) * 4 + (m & 3)] = sc * acc;
    }
}

// ---------------------------------------------------------------------------
// Packed f32x2 + cp.async helpers
// ---------------------------------------------------------------------------
__device__ __forceinline__ unsigned long long fma2(unsigned long long a,
                                                   unsigned long long b,
                                                   unsigned long long c) {
    unsigned long long d;
    asm("fma.rn.f32x2 %0, %1, %2, %3;" : "=l"(d) : "l"(a), "l"(b), "l"(c));
    return d;
}
__device__ __forceinline__ unsigned long long dup2(float v) {
    unsigned long long r;
    asm("mov.b64 %0, {%1, %1};" : "=l"(r) : "f"(v));
    return r;
}
__device__ __forceinline__ void unpack2(unsigned long long v, float& lo, float& hi) {
    asm("mov.b64 {%0, %1}, %2;" : "=f"(lo), "=f"(hi) : "l"(v));
}
__device__ __forceinline__ void cp_async16(unsigned smem_addr, const void* gptr) {
    asm volatile("cp.async.cg.shared.global [%0], [%1], 16;"
                 :: "r"(smem_addr), "l"(gptr) : "memory");
}
__device__ __forceinline__ void cp_commit() {
    asm volatile("cp.async.commit_group;" ::: "memory");
}
__device__ __forceinline__ void cp_wait() {
    asm volatile("cp.async.wait_group %0;" :: "n"(INFLIGHT) : "memory");
}

// ---------------------------------------------------------------------------
// Persistent main kernel (validated R14 config, unchanged):
//   y[row, (rho+3+128m)&2047] = sum_t x[row, rho+128t] * Wfin[t][m][rho]
// 152 CTAs (1/SM via 200 KB smem), 16 warp-private 8-stage cp.async rings,
// no block barriers; W resident ([t][m4][rho][4] -> float4 IS two fma2
// operands); __stcs epilogue (warp-contiguous 128 B runs). __maxnreg__(120).
// ---------------------------------------------------------------------------
#define SM_W      0
#define SM_X      (32 * 1024)                       // floats
#define SM_BIAS   (SM_X + 16 * STAGES * 128)        // + 16384 = 49152
#define SM_FLOATS (SM_BIAS + N)                     // 51200 floats = 200 KB

__global__ void __maxnreg__(120)
k_main(const float* __restrict__ x, const float* __restrict__ bias,
       float* __restrict__ y) {
    extern __shared__ float smem[];

    const int tid  = threadIdx.x;
    const int lane = tid & 31;
    const int warp = tid >> 5;
    const int grp  = warp >> 2;                 // 0..3 -> rows grp*4..grp*4+3
    const int wsub = warp & 3;                  // 32-rho window
    const int rho  = wsub * 32 + lane;
    const int crow = lane >> 3;                 // row this lane copies (0..3)
    const int coff = (lane & 7) * 4;            // float offset in 32-float window

    float* ring = smem + SM_X + warp * (STAGES * 128);
    const unsigned ring_sa = (unsigned)__cvta_generic_to_shared(ring)
                           + (unsigned)(crow * 32 + coff) * 4;
    const size_t lane_off = (size_t)(grp * 4 + crow) * N + wsub * 32 + coff;
    const size_t tile_step = (size_t)GRID_MAIN * RPB * N;

    int tile = blockIdx.x;
    const float* cur = x + (size_t)tile * RPB * N + lane_off;

    // Prologue FIRST (independent of Wfin): stages 0..6, 7 groups in flight.
#pragma unroll
    for (int s = 0; s < STAGES - 1; s++) {
        cp_async16(ring_sa + (unsigned)(s * 512), cur + s * 128);
        cp_commit();
    }

    // Bias is also compose-independent: load before the wait.
    for (int i = tid; i < N; i += THREADS) smem[SM_BIAS + i] = bias[i];

    // Wait for k_compose (g_Wfin visible)
    pdl_wait();

    // Resident W (float4)
    {
        const float4* src = (const float4*)g_Wfin;
        float4* dst = (float4*)(smem + SM_W);
#pragma unroll
        for (int i = tid; i < (K * K * 128) / 4; i += THREADS) dst[i] = src[i];
    }
    __syncthreads();

    for (; tile < NTILES; tile += GRID_MAIN) {
        const bool has_next = (tile + GRID_MAIN) < NTILES;
        const float* nxt = has_next ? cur + tile_step : cur;  // clamp: dummy re-read

        unsigned long long acc[4][8];
#pragma unroll
        for (int j = 0; j < 4; j++)
#pragma unroll
            for (int p = 0; p < 8; p++) acc[j][p] = 0ull;

#pragma unroll
        for (int t = 0; t < 16; t++) {
            cp_wait();
            __syncwarp();

            const float* xs = ring + (t & (STAGES - 1)) * 128;
            unsigned long long px0 = dup2(xs[lane]);
            unsigned long long px1 = dup2(xs[32 + lane]);
            unsigned long long px2 = dup2(xs[64 + lane]);
            unsigned long long px3 = dup2(xs[96 + lane]);

            // Refill: global stage t+7 (rolls into next tile at the tail)
            {
                const int s7 = t + (STAGES - 1);
                const float* src = (s7 < 16) ? (cur + s7 * 128)
                                             : (nxt + (s7 - 16) * 128);
                cp_async16(ring_sa + (unsigned)((s7 & (STAGES - 1)) * 512), src);
                cp_commit();
            }

            const float* wrow = smem + SM_W + t * 2048 + rho * 4;
#pragma unroll
            for (int m4 = 0; m4 < 4; m4++) {
                // float4 = two f32x2 operands for (m, m+1): no repacking
                ulonglong2 w = *(const ulonglong2*)(wrow + m4 * 512);
                acc[0][2 * m4]     = fma2(px0, w.x, acc[0][2 * m4]);
                acc[1][2 * m4]     = fma2(px1, w.x, acc[1][2 * m4]);
                acc[2][2 * m4]     = fma2(px2, w.x, acc[2][2 * m4]);
                acc[3][2 * m4]     = fma2(px3, w.x, acc[3][2 * m4]);
                acc[0][2 * m4 + 1] = fma2(px0, w.y, acc[0][2 * m4 + 1]);
                acc[1][2 * m4 + 1] = fma2(px1, w.y, acc[1][2 * m4 + 1]);
                acc[2][2 * m4 + 1] = fma2(px2, w.y, acc[2][2 * m4 + 1]);
                acc[3][2 * m4 + 1] = fma2(px3, w.y, acc[3][2 * m4 + 1]);
            }
        }
        cur = nxt;

        // Epilogue: bias + relu + streaming stores (warp-contiguous 128 B runs)
        float* yr = y + ((size_t)tile * RPB + grp * 4) * N;
#pragma unroll
        for (int p = 0; p < 8; p++) {
            const int c0 = (rho + 3 + 256 * p) & (N - 1);
            const int c1 = (c0 + 128) & (N - 1);
            const float b0 = smem[SM_BIAS + c0];
            const float b1 = smem[SM_BIAS + c1];
#pragma unroll
            for (int j = 0; j < 4; j++) {
                float lo, hi;
                unpack2(acc[j][p], lo, hi);
                __stcs(yr + (size_t)j * N + c0, fmaxf(lo + b0, 0.f));
                __stcs(yr + (size_t)j * N + c1, fmaxf(hi + b1, 0.f));
            }
        }
    }
}

// ---------------------------------------------------------------------------
// Launch: fast compose (16 blocks, smem-staged tables) then main with PDL.
// Inputs: x, vals0, vals1, vals2, rows0, cols0, rows1, cols1, rows2, cols2,
//         scaling, bias
// ---------------------------------------------------------------------------
extern "C" void kernel_launch(void* const* d_in, const int* in_sizes, int n_in,
                              void* d_out, int out_size) {
    const float* x       = (const float*)d_in[0];
    const float* v0      = (const float*)d_in[1];
    const float* v1      = (const float*)d_in[2];
    const float* v2      = (const float*)d_in[3];
    const float* scaling = (const float*)d_in[10];
    const float* bias    = (const float*)d_in[11];
    float* y = (float*)d_out;

    static int attr_set = 0;
    if (!attr_set) {
        cudaFuncSetAttribute(k_compose, cudaFuncAttributeMaxDynamicSharedMemorySize,
                             CSM_FLOATS * sizeof(float));
        cudaFuncSetAttribute(k_main, cudaFuncAttributeMaxDynamicSharedMemorySize,
                             SM_FLOATS * sizeof(float));
        attr_set = 1;
    }

    k_compose<<<16, 256, CSM_FLOATS * sizeof(float)>>>(v0, v1, v2, scaling);

    cudaLaunchConfig_t cfg = {};
    cfg.gridDim = dim3(GRID_MAIN, 1, 1);
    cfg.blockDim = dim3(THREADS, 1, 1);
    cfg.dynamicSmemBytes = SM_FLOATS * sizeof(float);
    cfg.stream = 0;
    cudaLaunchAttribute attr[1];
    attr[0].id = cudaLaunchAttributeProgrammaticStreamSerialization;
    attr[0].val.programmaticStreamSerializationAllowed = 1;
    cfg.attrs = attr;
    cfg.numAttrs = 1;
    cudaLaunchKernelEx(&cfg, k_main, x, bias, y);
}

// round 16
// speedup vs baseline: 1.1448x; 1.1448x over previous
#include <cuda_runtime.h>

#define N 2048
#define K 16
#define BATCH 16384
#define RPB 16
#define THREADS 512
#define GRID_MAIN 152
#define NTILES (BATCH / RPB)
#define STAGES 8
#define INFLIGHT 6   // wait_group 6 -> 7 groups (3.5 KB) in flight per warp

// Final composed weights, layout [t][m4][rho][4]:
//   g_Wfin[((t*4 + (m>>2))*128 + rho)*4 + (m&3)]
__device__ float g_Wfin[K * K * 128];

// ---------------------------------------------------------------------------
// PDL primitives
// ---------------------------------------------------------------------------
__device__ __forceinline__ void pdl_launch_dependents() {
    asm volatile("griddepcontrol.launch_dependents;" ::: "memory");
}
__device__ __forceinline__ void pdl_wait() {
    asm volatile("griddepcontrol.wait;" ::: "memory");
}

// ---------------------------------------------------------------------------
// Fused precompute (R5 form — the lowest-overhead round): 128 blocks x 256
// threads = 16 r x 16 s per block, W01 staged in smem, both stages in one
// kernel. launch_dependents first so k_main places immediately.
// Composed pattern: c = (r + 128*s + 3) % N; r = rho + 128*t, m = (t+s)&15.
// ---------------------------------------------------------------------------
__global__ void k_compose(const float* __restrict__ v0, const float* __restrict__ v1,
                          const float* __restrict__ v2, const float* __restrict__ scaling) {
    pdl_launch_dependents();

    __shared__ float w01[16][17];
    int s  = threadIdx.x & 15;
    int rl = threadIdx.x >> 4;
    int r  = blockIdx.x * 16 + rl;

    float acc = 0.f;
#pragma unroll
    for (int k0 = 0; k0 < K; k0++) {
        int arow = (r + 128 * k0) & (N - 1);
        acc = fmaf(v0[r * K + k0], v1[arow * K + ((s - k0) & (K - 1))], acc);
    }
    w01[rl][s] = acc;
    __syncthreads();

    float sc = scaling[0];
    float acc2 = 0.f;
#pragma unroll
    for (int s01 = 0; s01 < K; s01++) {
        int brow = (r + 128 * s01 + 1) & (N - 1);
        acc2 = fmaf(w01[rl][s01], v2[brow * K + ((s - s01) & (K - 1))], acc2);
    }
    int rho = r & 127;
    int t   = r >> 7;
    int m   = (t + s) & (K - 1);
    g_Wfin[((t * 4 + (m >> 2)) * 128 + rho) * 4 + (m & 3)] = sc * acc2;
}

// ---------------------------------------------------------------------------
// Packed f32x2 + cp.async helpers
// ---------------------------------------------------------------------------
__device__ __forceinline__ unsigned long long fma2(unsigned long long a,
                                                   unsigned long long b,
                                                   unsigned long long c) {
    unsigned long long d;
    asm("fma.rn.f32x2 %0, %1, %2, %3;" : "=l"(d) : "l"(a), "l"(b), "l"(c));
    return d;
}
__device__ __forceinline__ unsigned long long dup2(float v) {
    unsigned long long r;
    asm("mov.b64 %0, {%1, %1};" : "=l"(r) : "f"(v));
    return r;
}
__device__ __forceinline__ void unpack2(unsigned long long v, float& lo, float& hi) {
    asm("mov.b64 {%0, %1}, %2;" : "=f"(lo), "=f"(hi) : "l"(v));
}
__device__ __forceinline__ void cp_async16(unsigned smem_addr, const void* gptr) {
    asm volatile("cp.async.cg.shared.global [%0], [%1], 16;"
                 :: "r"(smem_addr), "l"(gptr) : "memory");
}
__device__ __forceinline__ void cp_commit() {
    asm volatile("cp.async.commit_group;" ::: "memory");
}
__device__ __forceinline__ void cp_wait() {
    asm volatile("cp.async.wait_group %0;" :: "n"(INFLIGHT) : "memory");
}

// ---------------------------------------------------------------------------
// Persistent main kernel (R14 config — best measured main, 47.9 us):
//   y[row, (rho+3+128m)&2047] = sum_t x[row, rho+128t] * Wfin[t][m][rho]
// 152 CTAs (1/SM via 200 KB smem), 16 warp-private 8-stage cp.async rings,
// no block barriers; W resident ([t][m4][rho][4] -> float4 IS two fma2
// operands); __stcs epilogue. __maxnreg__(120).
// R16 delta: PREDICATED tail refill — no dummy re-reads past the last tile
// (commit still issued to keep wait_group counts aligned).
// ---------------------------------------------------------------------------
#define SM_W      0
#define SM_X      (32 * 1024)                       // floats
#define SM_BIAS   (SM_X + 16 * STAGES * 128)        // + 16384 = 49152
#define SM_FLOATS (SM_BIAS + N)                     // 51200 floats = 200 KB

__global__ void __maxnreg__(120)
k_main(const float* __restrict__ x, const float* __restrict__ bias,
       float* __restrict__ y) {
    extern __shared__ float smem[];

    const int tid  = threadIdx.x;
    const int lane = tid & 31;
    const int warp = tid >> 5;
    const int grp  = warp >> 2;                 // 0..3 -> rows grp*4..grp*4+3
    const int wsub = warp & 3;                  // 32-rho window
    const int rho  = wsub * 32 + lane;
    const int crow = lane >> 3;                 // row this lane copies (0..3)
    const int coff = (lane & 7) * 4;            // float offset in 32-float window

    float* ring = smem + SM_X + warp * (STAGES * 128);
    const unsigned ring_sa = (unsigned)__cvta_generic_to_shared(ring)
                           + (unsigned)(crow * 32 + coff) * 4;
    const size_t lane_off = (size_t)(grp * 4 + crow) * N + wsub * 32 + coff;
    const size_t tile_step = (size_t)GRID_MAIN * RPB * N;

    int tile = blockIdx.x;
    const float* cur = x + (size_t)tile * RPB * N + lane_off;

    // Prologue FIRST (independent of Wfin): stages 0..6, 7 groups in flight.
#pragma unroll
    for (int s = 0; s < STAGES - 1; s++) {
        cp_async16(ring_sa + (unsigned)(s * 512), cur + s * 128);
        cp_commit();
    }

    // Bias is compose-independent: load before the wait.
    for (int i = tid; i < N; i += THREADS) smem[SM_BIAS + i] = bias[i];

    // Wait for k_compose (g_Wfin visible)
    pdl_wait();

    // Resident W (float4)
    {
        const float4* src = (const float4*)g_Wfin;
        float4* dst = (float4*)(smem + SM_W);
#pragma unroll
        for (int i = tid; i < (K * K * 128) / 4; i += THREADS) dst[i] = src[i];
    }
    __syncthreads();

    for (; tile < NTILES; tile += GRID_MAIN) {
        const bool has_next = (tile + GRID_MAIN) < NTILES;
        const float* nxt = cur + tile_step;

        unsigned long long acc[4][8];
#pragma unroll
        for (int j = 0; j < 4; j++)
#pragma unroll
            for (int p = 0; p < 8; p++) acc[j][p] = 0ull;

#pragma unroll
        for (int t = 0; t < 16; t++) {
            cp_wait();
            __syncwarp();

            const float* xs = ring + (t & (STAGES - 1)) * 128;
            unsigned long long px0 = dup2(xs[lane]);
            unsigned long long px1 = dup2(xs[32 + lane]);
            unsigned long long px2 = dup2(xs[64 + lane]);
            unsigned long long px3 = dup2(xs[96 + lane]);

            // Refill: global stage t+7. Predicated at the tail: no dummy
            // re-reads past the last tile; empty commit keeps counts aligned.
            {
                const int s7 = t + (STAGES - 1);
                if (s7 < 16) {
                    cp_async16(ring_sa + (unsigned)((s7 & (STAGES - 1)) * 512),
                               cur + s7 * 128);
                } else if (has_next) {
                    cp_async16(ring_sa + (unsigned)((s7 & (STAGES - 1)) * 512),
                               nxt + (s7 - 16) * 128);
                }
                cp_commit();
            }

            const float* wrow = smem + SM_W + t * 2048 + rho * 4;
#pragma unroll
            for (int m4 = 0; m4 < 4; m4++) {
                // float4 = two f32x2 operands for (m, m+1): no repacking
                ulonglong2 w = *(const ulonglong2*)(wrow + m4 * 512);
                acc[0][2 * m4]     = fma2(px0, w.x, acc[0][2 * m4]);
                acc[1][2 * m4]     = fma2(px1, w.x, acc[1][2 * m4]);
                acc[2][2 * m4]     = fma2(px2, w.x, acc[2][2 * m4]);
                acc[3][2 * m4]     = fma2(px3, w.x, acc[3][2 * m4]);
                acc[0][2 * m4 + 1] = fma2(px0, w.y, acc[0][2 * m4 + 1]);
                acc[1][2 * m4 + 1] = fma2(px1, w.y, acc[1][2 * m4 + 1]);
                acc[2][2 * m4 + 1] = fma2(px2, w.y, acc[2][2 * m4 + 1]);
                acc[3][2 * m4 + 1] = fma2(px3, w.y, acc[3][2 * m4 + 1]);
            }
        }
        cur = nxt;

        // Epilogue: bias + relu + streaming stores (warp-contiguous 128 B runs)
        float* yr = y + ((size_t)tile * RPB + grp * 4) * N;
#pragma unroll
        for (int p = 0; p < 8; p++) {
            const int c0 = (rho + 3 + 256 * p) & (N - 1);
            const int c1 = (c0 + 128) & (N - 1);
            const float b0 = smem[SM_BIAS + c0];
            const float b1 = smem[SM_BIAS + c1];
#pragma unroll
            for (int j = 0; j < 4; j++) {
                float lo, hi;
                unpack2(acc[j][p], lo, hi);
                __stcs(yr + (size_t)j * N + c0, fmaxf(lo + b0, 0.f));
                __stcs(yr + (size_t)j * N + c1, fmaxf(hi + b1, 0.f));
            }
        }
    }
}

// ---------------------------------------------------------------------------
// Launch: compose (128 blocks x 256 thr) then main with PDL.
// Inputs: x, vals0, vals1, vals2, rows0, cols0, rows1, cols1, rows2, cols2,
//         scaling, bias
// ---------------------------------------------------------------------------
extern "C" void kernel_launch(void* const* d_in, const int* in_sizes, int n_in,
                              void* d_out, int out_size) {
    const float* x       = (const float*)d_in[0];
    const float* v0      = (const float*)d_in[1];
    const float* v1      = (const float*)d_in[2];
    const float* v2      = (const float*)d_in[3];
    const float* scaling = (const float*)d_in[10];
    const float* bias    = (const float*)d_in[11];
    float* y = (float*)d_out;

    static int attr_set = 0;
    if (!attr_set) {
        cudaFuncSetAttribute(k_main, cudaFuncAttributeMaxDynamicSharedMemorySize,
                             SM_FLOATS * sizeof(float));
        attr_set = 1;
    }

    k_compose<<<N / 16, 256>>>(v0, v1, v2, scaling);

    cudaLaunchConfig_t cfg = {};
    cfg.gridDim = dim3(GRID_MAIN, 1, 1);
    cfg.blockDim = dim3(THREADS, 1, 1);
    cfg.dynamicSmemBytes = SM_FLOATS * sizeof(float);
    cfg.stream = 0;
    cudaLaunchAttribute attr[1];
    attr[0].id = cudaLaunchAttributeProgrammaticStreamSerialization;
    attr[0].val.programmaticStreamSerializationAllowed = 1;
    cfg.attrs = attr;
    cfg.numAttrs = 1;
    cudaLaunchKernelEx(&cfg, k_main, x, bias, y);
}

// round 17
// speedup vs baseline: 1.1468x; 1.0017x over previous
#include <cuda_runtime.h>

#define N 2048
#define K 16
#define BATCH 16384
#define RPB 16
#define THREADS 512
#define GRID_MAIN 152
#define NTILES (BATCH / RPB)
#define STAGES 8
#define INFLIGHT 6   // wait_group 6 -> 7 groups (3.5 KB) in flight per warp

// Final composed weights, layout [t][m4][rho][4]:
//   g_Wfin[((t*4 + (m>>2))*128 + rho)*4 + (m&3)]
__device__ float g_Wfin[K * K * 128];

// ---------------------------------------------------------------------------
// PDL primitives
// ---------------------------------------------------------------------------
__device__ __forceinline__ void pdl_launch_dependents() {
    asm volatile("griddepcontrol.launch_dependents;" ::: "memory");
}
__device__ __forceinline__ void pdl_wait() {
    asm volatile("griddepcontrol.wait;" ::: "memory");
}

// ---------------------------------------------------------------------------
// Fused precompute (128 blocks x 256 thr — the lowest-gap configuration):
// 16 r x 16 s per block, W01 staged in smem, both stages in one kernel.
// launch_dependents first so k_main places immediately.
// Composed pattern: c = (r + 128*s + 3) % N; r = rho + 128*t, m = (t+s)&15.
// ---------------------------------------------------------------------------
__global__ void k_compose(const float* __restrict__ v0, const float* __restrict__ v1,
                          const float* __restrict__ v2, const float* __restrict__ scaling) {
    pdl_launch_dependents();

    __shared__ float w01[16][17];
    int s  = threadIdx.x & 15;
    int rl = threadIdx.x >> 4;
    int r  = blockIdx.x * 16 + rl;

    float acc = 0.f;
#pragma unroll
    for (int k0 = 0; k0 < K; k0++) {
        int arow = (r + 128 * k0) & (N - 1);
        acc = fmaf(v0[r * K + k0], v1[arow * K + ((s - k0) & (K - 1))], acc);
    }
    w01[rl][s] = acc;
    __syncthreads();

    float sc = scaling[0];
    float acc2 = 0.f;
#pragma unroll
    for (int s01 = 0; s01 < K; s01++) {
        int brow = (r + 128 * s01 + 1) & (N - 1);
        acc2 = fmaf(w01[rl][s01], v2[brow * K + ((s - s01) & (K - 1))], acc2);
    }
    int rho = r & 127;
    int t   = r >> 7;
    int m   = (t + s) & (K - 1);
    g_Wfin[((t * 4 + (m >> 2)) * 128 + rho) * 4 + (m & 3)] = sc * acc2;
}

// ---------------------------------------------------------------------------
// Packed f32x2 + cp.async helpers
// ---------------------------------------------------------------------------
__device__ __forceinline__ unsigned long long fma2(unsigned long long a,
                                                   unsigned long long b,
                                                   unsigned long long c) {
    unsigned long long d;
    asm("fma.rn.f32x2 %0, %1, %2, %3;" : "=l"(d) : "l"(a), "l"(b), "l"(c));
    return d;
}
__device__ __forceinline__ unsigned long long dup2(float v) {
    unsigned long long r;
    asm("mov.b64 %0, {%1, %1};" : "=l"(r) : "f"(v));
    return r;
}
__device__ __forceinline__ void unpack2(unsigned long long v, float& lo, float& hi) {
    asm("mov.b64 {%0, %1}, %2;" : "=f"(lo), "=f"(hi) : "l"(v));
}
__device__ __forceinline__ void cp_async16(unsigned smem_addr, const void* gptr) {
    asm volatile("cp.async.cg.shared.global [%0], [%1], 16;"
                 :: "r"(smem_addr), "l"(gptr) : "memory");
}
__device__ __forceinline__ void cp_commit() {
    asm volatile("cp.async.commit_group;" ::: "memory");
}
__device__ __forceinline__ void cp_wait() {
    asm volatile("cp.async.wait_group %0;" :: "n"(INFLIGHT) : "memory");
}

// ---------------------------------------------------------------------------
// Persistent main kernel (R16 base = best measured config):
//   y[row, (rho+3+128m)&2047] = sum_t x[row, rho+128t] * Wfin[t][m][rho]
// 152 CTAs (1/SM via smem), 16 warp-private 8-stage cp.async rings, no block
// barriers; W resident ([t][m4][rho][4] -> float4 IS two fma2 operands);
// predicated tail refill; __maxnreg__(120); PDL wait after the x prologue.
//
// R17 deltas:
//  - bias staged PRE-SHIFTED: smem_bias[i] = bias[(i+3)&2047], i = 128m+rho
//    -> epilogue bias LDS is lane-linear, conflict-free, no address math.
//  - store order j (row) outer, p (column pair) inner -> each row's stores
//    walk ascending columns: longer sequential write runs per DRAM page.
// ---------------------------------------------------------------------------
#define SM_W      0
#define SM_X      (32 * 1024)                       // floats
#define SM_BIAS   (SM_X + 16 * STAGES * 128)        // + 16384 = 49152
#define SM_FLOATS (SM_BIAS + N)                     // 51200 floats = 200 KB

__global__ void __maxnreg__(120)
k_main(const float* __restrict__ x, const float* __restrict__ bias,
       float* __restrict__ y) {
    extern __shared__ float smem[];

    const int tid  = threadIdx.x;
    const int lane = tid & 31;
    const int warp = tid >> 5;
    const int grp  = warp >> 2;                 // 0..3 -> rows grp*4..grp*4+3
    const int wsub = warp & 3;                  // 32-rho window
    const int rho  = wsub * 32 + lane;
    const int crow = lane >> 3;                 // row this lane copies (0..3)
    const int coff = (lane & 7) * 4;            // float offset in 32-float window

    float* ring = smem + SM_X + warp * (STAGES * 128);
    const unsigned ring_sa = (unsigned)__cvta_generic_to_shared(ring)
                           + (unsigned)(crow * 32 + coff) * 4;
    const size_t lane_off = (size_t)(grp * 4 + crow) * N + wsub * 32 + coff;
    const size_t tile_step = (size_t)GRID_MAIN * RPB * N;

    int tile = blockIdx.x;
    const float* cur = x + (size_t)tile * RPB * N + lane_off;

    // Prologue FIRST (independent of Wfin): stages 0..6, 7 groups in flight.
#pragma unroll
    for (int s = 0; s < STAGES - 1; s++) {
        cp_async16(ring_sa + (unsigned)(s * 512), cur + s * 128);
        cp_commit();
    }

    // Bias (compose-independent), PRE-SHIFTED layout: smem[i] = bias[(i+3)%N]
    // so index 128m+rho directly yields bias[(rho+3+128m)&2047].
    for (int i = tid; i < N; i += THREADS)
        smem[SM_BIAS + i] = bias[(i + 3) & (N - 1)];

    // Wait for k_compose (g_Wfin visible)
    pdl_wait();

    // Resident W (float4)
    {
        const float4* src = (const float4*)g_Wfin;
        float4* dst = (float4*)(smem + SM_W);
#pragma unroll
        for (int i = tid; i < (K * K * 128) / 4; i += THREADS) dst[i] = src[i];
    }
    __syncthreads();

    for (; tile < NTILES; tile += GRID_MAIN) {
        const bool has_next = (tile + GRID_MAIN) < NTILES;
        const float* nxt = cur + tile_step;

        unsigned long long acc[4][8];
#pragma unroll
        for (int j = 0; j < 4; j++)
#pragma unroll
            for (int p = 0; p < 8; p++) acc[j][p] = 0ull;

#pragma unroll
        for (int t = 0; t < 16; t++) {
            cp_wait();
            __syncwarp();

            const float* xs = ring + (t & (STAGES - 1)) * 128;
            unsigned long long px0 = dup2(xs[lane]);
            unsigned long long px1 = dup2(xs[32 + lane]);
            unsigned long long px2 = dup2(xs[64 + lane]);
            unsigned long long px3 = dup2(xs[96 + lane]);

            // Refill: global stage t+7. Predicated at the tail: no dummy
            // re-reads past the last tile; empty commit keeps counts aligned.
            {
                const int s7 = t + (STAGES - 1);
                if (s7 < 16) {
                    cp_async16(ring_sa + (unsigned)((s7 & (STAGES - 1)) * 512),
                               cur + s7 * 128);
                } else if (has_next) {
                    cp_async16(ring_sa + (unsigned)((s7 & (STAGES - 1)) * 512),
                               nxt + (s7 - 16) * 128);
                }
                cp_commit();
            }

            const float* wrow = smem + SM_W + t * 2048 + rho * 4;
#pragma unroll
            for (int m4 = 0; m4 < 4; m4++) {
                // float4 = two f32x2 operands for (m, m+1): no repacking
                ulonglong2 w = *(const ulonglong2*)(wrow + m4 * 512);
                acc[0][2 * m4]     = fma2(px0, w.x, acc[0][2 * m4]);
                acc[1][2 * m4]     = fma2(px1, w.x, acc[1][2 * m4]);
                acc[2][2 * m4]     = fma2(px2, w.x, acc[2][2 * m4]);
                acc[3][2 * m4]     = fma2(px3, w.x, acc[3][2 * m4]);
                acc[0][2 * m4 + 1] = fma2(px0, w.y, acc[0][2 * m4 + 1]);
                acc[1][2 * m4 + 1] = fma2(px1, w.y, acc[1][2 * m4 + 1]);
                acc[2][2 * m4 + 1] = fma2(px2, w.y, acc[2][2 * m4 + 1]);
                acc[3][2 * m4 + 1] = fma2(px3, w.y, acc[3][2 * m4 + 1]);
            }
        }
        cur = nxt;

        // Epilogue: row-outer / column-pair-inner -> ascending-column
        // sequential writes per row (DRAM page friendly). Bias LDS is
        // lane-linear thanks to the pre-shifted table.
        float* yr = y + ((size_t)tile * RPB + grp * 4) * N;
#pragma unroll
        for (int j = 0; j < 4; j++) {
            float* yj = yr + (size_t)j * N;
#pragma unroll
            for (int p = 0; p < 8; p++) {
                const int c0 = (rho + 3 + 256 * p) & (N - 1);
                const int c1 = (c0 + 128) & (N - 1);
                const float b0 = smem[SM_BIAS + p * 256 + rho];
                const float b1 = smem[SM_BIAS + p * 256 + 128 + rho];
                float lo, hi;
                unpack2(acc[j][p], lo, hi);
                __stcs(yj + c0, fmaxf(lo + b0, 0.f));
                __stcs(yj + c1, fmaxf(hi + b1, 0.f));
            }
        }
    }
}

// ---------------------------------------------------------------------------
// Launch: compose (128 blocks x 256 thr) then main with PDL.
// Inputs: x, vals0, vals1, vals2, rows0, cols0, rows1, cols1, rows2, cols2,
//         scaling, bias
// ---------------------------------------------------------------------------
extern "C" void kernel_launch(void* const* d_in, const int* in_sizes, int n_in,
                              void* d_out, int out_size) {
    const float* x       = (const float*)d_in[0];
    const float* v0      = (const float*)d_in[1];
    const float* v1      = (const float*)d_in[2];
    const float* v2      = (const float*)d_in[3];
    const float* scaling = (const float*)d_in[10];
    const float* bias    = (const float*)d_in[11];
    float* y = (float*)d_out;

    static int attr_set = 0;
    if (!attr_set) {
        cudaFuncSetAttribute(k_main, cudaFuncAttributeMaxDynamicSharedMemorySize,
                             SM_FLOATS * sizeof(float));
        attr_set = 1;
    }

    k_compose<<<N / 16, 256>>>(v0, v1, v2, scaling);

    cudaLaunchConfig_t cfg = {};
    cfg.gridDim = dim3(GRID_MAIN, 1, 1);
    cfg.blockDim = dim3(THREADS, 1, 1);
    cfg.dynamicSmemBytes = SM_FLOATS * sizeof(float);
    cfg.stream = 0;
    cudaLaunchAttribute attr[1];
    attr[0].id = cudaLaunchAttributeProgrammaticStreamSerialization;
    attr[0].val.programmaticStreamSerializationAllowed = 1;
    cfg.attrs = attr;
    cfg.numAttrs = 1;
    cudaLaunchKernelEx(&cfg, k_main, x, bias, y);
}